// round 2
// baseline (speedup 1.0000x reference)
#include <cuda_runtime.h>
#include <math.h>

#define NB   8
#define LOW  64
#define NN   4096
#define HID  16

// ----------------- device scratch (no allocations allowed) -----------------
__device__ __align__(16) float g_xl[NB*NN];
__device__ __align__(16) float g_h1[NB*64*NN];
__device__ __align__(16) float g_nodes[NB*NN*HID];
__device__ __align__(16) float g_sq[NB*NN];
__device__ __align__(16) float g_xp[NB*NN*HID];
__device__ __align__(16) float g_asr[NB*NN*4];
__device__ __align__(16) float g_adt[NB*NN*4];
__device__ __align__(16) float g_p[NB*NN*HID];
__device__ __align__(16) float g_outlow[NB*NN];
__device__ __align__(16) float g_w1t[9*64];
__device__ __align__(16) float g_beta1[64];
__device__ __align__(16) float g_Wt2[64*9*16];
__device__ __align__(16) float g_beta2[16];
__device__ __align__(16) float g_Wu2t[128*16];

// ----------------- packed f32x2 helpers -----------------
__device__ __forceinline__ unsigned long long ffma2(unsigned long long a,
                                                    unsigned long long b,
                                                    unsigned long long c) {
    unsigned long long d;
    asm("fma.rn.f32x2 %0, %1, %2, %3;" : "=l"(d) : "l"(a), "l"(b), "l"(c));
    return d;
}
__device__ __forceinline__ unsigned long long pk2(float lo, float hi) {
    unsigned long long u;
    asm("mov.b64 %0, {%1, %2};" : "=l"(u) : "r"(__float_as_uint(lo)), "r"(__float_as_uint(hi)));
    return u;
}
__device__ __forceinline__ float unpksum(unsigned long long u) {
    float a, b;
    asm("mov.b64 {%0, %1}, %2;" : "=f"(a), "=f"(b) : "l"(u));
    return a + b;
}

// ----------------- prep: fold BN, transpose weights -----------------
__global__ void prepk(const float* __restrict__ W1, const float* __restrict__ b1,
                      const float* __restrict__ g1, const float* __restrict__ be1,
                      const float* __restrict__ m1, const float* __restrict__ v1,
                      const float* __restrict__ W2, const float* __restrict__ b2,
                      const float* __restrict__ g2, const float* __restrict__ be2,
                      const float* __restrict__ m2, const float* __restrict__ v2,
                      const float* __restrict__ Wu2)
{
    __shared__ float a2[16];
    int t = threadIdx.x;
    if (t < 64) {
        float a = g1[t] / sqrtf(v1[t] + 1e-5f);
        g_beta1[t] = (b1[t] - m1[t]) * a + be1[t];
        #pragma unroll
        for (int tp = 0; tp < 9; tp++) g_w1t[tp*64 + t] = W1[t*9 + tp] * a;
    }
    if (t < 16) {
        float a = g2[t] / sqrtf(v2[t] + 1e-5f);
        a2[t] = a;
        g_beta2[t] = (b2[t] - m2[t]) * a + be2[t];
    }
    __syncthreads();
    for (int i = t; i < 64*9*16; i += 256) {
        int oc = i & 15; int rest = i >> 4; int tp = rest % 9; int ci = rest / 9;
        g_Wt2[i] = W2[(oc*64 + ci)*9 + tp] * a2[oc];
    }
    for (int i = t; i < 2048; i += 256) {
        int h = i >> 4, o = i & 15;
        g_Wu2t[i] = Wu2[o*128 + h];
    }
}

// ----------------- antialiased bilinear 256 -> 64 (jax semantics) -----------------
__global__ void downk(const float* __restrict__ x)
{
    int idx = blockIdx.x * 256 + threadIdx.x;            // 32768
    int b = idx >> 12, oy = (idx >> 6) & 63, ox = idx & 63;
    float wy[8], wx[8]; float sy = 0.f, sx = 0.f;
    #pragma unroll
    for (int d = 0; d < 8; d++) {
        float w = 1.f - 0.25f * fabsf((float)d - 3.5f);
        int jy = 4*oy + d - 2;
        int jx = 4*ox + d - 2;
        wy[d] = (jy >= 0 && jy < 256) ? w : 0.f; sy += wy[d];
        wx[d] = (jx >= 0 && jx < 256) ? w : 0.f; sx += wx[d];
    }
    const float* src = x + (size_t)b * 65536;
    float acc = 0.f;
    #pragma unroll
    for (int dy = 0; dy < 8; dy++) {
        int jy = 4*oy + dy - 2; jy = jy < 0 ? 0 : (jy > 255 ? 255 : jy);
        float rowacc = 0.f;
        #pragma unroll
        for (int dx = 0; dx < 8; dx++) {
            int jx = 4*ox + dx - 2; jx = jx < 0 ? 0 : (jx > 255 ? 255 : jx);
            rowacc = fmaf(wx[dx], src[jy*256 + jx], rowacc);
        }
        acc = fmaf(wy[dy], rowacc, acc);
    }
    g_xl[idx] = acc / (sy * sx);
}

// ----------------- conv1: 1->64, 3x3 SAME, BN+ReLU folded -----------------
__global__ void conv1k()
{
    __shared__ __align__(16) float sw[576];
    __shared__ __align__(16) float sb[64];
    int t = threadIdx.x;
    for (int i = t; i < 576; i += 256) sw[i] = g_w1t[i];
    if (t < 64) sb[t] = g_beta1[t];
    __syncthreads();
    int idx = blockIdx.x * 256 + t;
    int b = idx >> 12, y = (idx >> 6) & 63, xx = idx & 63;
    float vin[9];
    #pragma unroll
    for (int dy = 0; dy < 3; dy++)
        #pragma unroll
        for (int dx = 0; dx < 3; dx++) {
            int yy = y + dy - 1, xc = xx + dx - 1;
            vin[dy*3+dx] = (yy >= 0 && yy < 64 && xc >= 0 && xc < 64)
                           ? g_xl[b*4096 + yy*64 + xc] : 0.f;
        }
    const float4* sw4 = (const float4*)sw;
    const float4* sb4 = (const float4*)sb;
    #pragma unroll
    for (int o4 = 0; o4 < 16; o4++) {
        float4 a = sb4[o4];
        #pragma unroll
        for (int tp = 0; tp < 9; tp++) {
            float v = vin[tp];
            float4 wv = sw4[tp*16 + o4];
            a.x = fmaf(v, wv.x, a.x); a.y = fmaf(v, wv.y, a.y);
            a.z = fmaf(v, wv.z, a.z); a.w = fmaf(v, wv.w, a.w);
        }
        size_t base = (((size_t)b*64 + o4*4)*64 + y)*64 + xx;
        g_h1[base        ] = fmaxf(a.x, 0.f);
        g_h1[base +  4096] = fmaxf(a.y, 0.f);
        g_h1[base +  8192] = fmaxf(a.z, 0.f);
        g_h1[base + 12288] = fmaxf(a.w, 0.f);
    }
}

// ----------------- conv2: 64->16, 3x3 SAME, BN+ReLU -> nodes + sq -----------------
__global__ void conv2k()
{
    __shared__ __align__(16) float swt[64*9*16];   // 36 KB
    __shared__ float tile[8*18*18];                // 10.1 KB
    __shared__ float sbeta[16];
    int t = threadIdx.x;
    for (int i = t; i < 9216; i += 256) swt[i] = g_Wt2[i];
    if (t < 16) sbeta[t] = g_beta2[t];
    int b = blockIdx.z; int y0 = blockIdx.y * 16; int x0 = blockIdx.x * 16;
    int ty = t >> 4, tx = t & 15;
    float4 acc0 = {0,0,0,0}, acc1 = {0,0,0,0}, acc2 = {0,0,0,0}, acc3 = {0,0,0,0};
    for (int cc = 0; cc < 8; cc++) {
        __syncthreads();
        for (int i = t; i < 2592; i += 256) {
            int cl = i / 324; int rem = i - cl*324; int rr = rem / 18; int c = rem - rr*18;
            int yy = y0 + rr - 1, xc = x0 + c - 1;
            float v = 0.f;
            if (yy >= 0 && yy < 64 && xc >= 0 && xc < 64)
                v = g_h1[(((size_t)b*64 + (cc*8 + cl))*64 + yy)*64 + xc];
            tile[i] = v;
        }
        __syncthreads();
        #pragma unroll
        for (int cl = 0; cl < 8; cl++) {
            int ci = cc*8 + cl;
            float v[9];
            #pragma unroll
            for (int dy = 0; dy < 3; dy++)
                #pragma unroll
                for (int dx = 0; dx < 3; dx++)
                    v[dy*3+dx] = tile[cl*324 + (ty+dy)*18 + (tx+dx)];
            const float4* w4 = (const float4*)&swt[ci*144];
            #pragma unroll
            for (int tp = 0; tp < 9; tp++) {
                float vv = v[tp];
                float4 wa = w4[tp*4+0], wb = w4[tp*4+1], wc = w4[tp*4+2], wd = w4[tp*4+3];
                acc0.x = fmaf(vv, wa.x, acc0.x); acc0.y = fmaf(vv, wa.y, acc0.y);
                acc0.z = fmaf(vv, wa.z, acc0.z); acc0.w = fmaf(vv, wa.w, acc0.w);
                acc1.x = fmaf(vv, wb.x, acc1.x); acc1.y = fmaf(vv, wb.y, acc1.y);
                acc1.z = fmaf(vv, wb.z, acc1.z); acc1.w = fmaf(vv, wb.w, acc1.w);
                acc2.x = fmaf(vv, wc.x, acc2.x); acc2.y = fmaf(vv, wc.y, acc2.y);
                acc2.z = fmaf(vv, wc.z, acc2.z); acc2.w = fmaf(vv, wc.w, acc2.w);
                acc3.x = fmaf(vv, wd.x, acc3.x); acc3.y = fmaf(vv, wd.y, acc3.y);
                acc3.z = fmaf(vv, wd.z, acc3.z); acc3.w = fmaf(vv, wd.w, acc3.w);
            }
        }
    }
    float out[16];
    out[0]=acc0.x; out[1]=acc0.y; out[2]=acc0.z; out[3]=acc0.w;
    out[4]=acc1.x; out[5]=acc1.y; out[6]=acc1.z; out[7]=acc1.w;
    out[8]=acc2.x; out[9]=acc2.y; out[10]=acc2.z; out[11]=acc2.w;
    out[12]=acc3.x; out[13]=acc3.y; out[14]=acc3.z; out[15]=acc3.w;
    float s = 0.f;
    #pragma unroll
    for (int c = 0; c < 16; c++) {
        float vv = fmaxf(out[c] + sbeta[c], 0.f);
        out[c] = vv; s = fmaf(vv, vv, s);
    }
    int n = (y0 + ty)*64 + (x0 + tx);
    float4* dst = (float4*)&g_nodes[((size_t)b*NN + n)*16];
    dst[0] = make_float4(out[0],out[1],out[2],out[3]);
    dst[1] = make_float4(out[4],out[5],out[6],out[7]);
    dst[2] = make_float4(out[8],out[9],out[10],out[11]);
    dst[3] = make_float4(out[12],out[13],out[14],out[15]);
    g_sq[(size_t)b*NN + n] = s;
}

// ----------------- GAT feature transform -----------------
__global__ void featk(const float* __restrict__ Wg, const float* __restrict__ a_src,
                      const float* __restrict__ a_dst)
{
    __shared__ float sWg[256];
    __shared__ float ssrc[16], sdst[16];
    int t = threadIdx.x;
    sWg[t] = Wg[t];
    if (t < 16) { ssrc[t] = a_src[t]; sdst[t] = a_dst[t]; }
    __syncthreads();
    int idx = blockIdx.x * 256 + t;                 // 32768 nodes total
    const float4* np = (const float4*)&g_nodes[(size_t)idx*16];
    float n[16];
    float4 v0 = np[0], v1 = np[1], v2 = np[2], v3 = np[3];
    n[0]=v0.x; n[1]=v0.y; n[2]=v0.z; n[3]=v0.w;
    n[4]=v1.x; n[5]=v1.y; n[6]=v1.z; n[7]=v1.w;
    n[8]=v2.x; n[9]=v2.y; n[10]=v2.z; n[11]=v2.w;
    n[12]=v3.x; n[13]=v3.y; n[14]=v3.z; n[15]=v3.w;
    float xo[16];
    #pragma unroll
    for (int o = 0; o < 16; o++) {
        float a = 0.f;
        #pragma unroll
        for (int c = 0; c < 16; c++) a = fmaf(n[c], sWg[o*16 + c], a);
        xo[o] = a;
    }
    float4* xpd = (float4*)&g_xp[(size_t)idx*16];
    xpd[0] = make_float4(xo[0],xo[1],xo[2],xo[3]);
    xpd[1] = make_float4(xo[4],xo[5],xo[6],xo[7]);
    xpd[2] = make_float4(xo[8],xo[9],xo[10],xo[11]);
    xpd[3] = make_float4(xo[12],xo[13],xo[14],xo[15]);
    float4 av, dv;
    av.x = xo[0]*ssrc[0] + xo[1]*ssrc[1] + xo[2]*ssrc[2] + xo[3]*ssrc[3];
    av.y = xo[4]*ssrc[4] + xo[5]*ssrc[5] + xo[6]*ssrc[6] + xo[7]*ssrc[7];
    av.z = xo[8]*ssrc[8] + xo[9]*ssrc[9] + xo[10]*ssrc[10] + xo[11]*ssrc[11];
    av.w = xo[12]*ssrc[12] + xo[13]*ssrc[13] + xo[14]*ssrc[14] + xo[15]*ssrc[15];
    dv.x = xo[0]*sdst[0] + xo[1]*sdst[1] + xo[2]*sdst[2] + xo[3]*sdst[3];
    dv.y = xo[4]*sdst[4] + xo[5]*sdst[5] + xo[6]*sdst[6] + xo[7]*sdst[7];
    dv.z = xo[8]*sdst[8] + xo[9]*sdst[9] + xo[10]*sdst[10] + xo[11]*sdst[11];
    dv.w = xo[12]*sdst[12] + xo[13]*sdst[13] + xo[14]*sdst[14] + xo[15]*sdst[15];
    ((float4*)g_asr)[idx] = av;
    ((float4*)g_adt)[idx] = dv;
}

// ----------------- kNN (top-8) + GAT aggregation -----------------
__global__ void __launch_bounds__(256) knnk(const float* __restrict__ bg)
{
    __shared__ __align__(16) float4 scand[512];    // 128 candidates x 16 floats
    __shared__ float ssq[128];
    int t = threadIdx.x;
    int b = blockIdx.y;
    int row = blockIdx.x * 256 + t;
    const float4* myp = (const float4*)g_nodes + ((size_t)b*NN + row)*4;
    float4 f0 = myp[0], f1 = myp[1], f2 = myp[2], f3 = myp[3];
    unsigned long long r[8];
    r[0]=pk2(f0.x,f0.y); r[1]=pk2(f0.z,f0.w);
    r[2]=pk2(f1.x,f1.y); r[3]=pk2(f1.z,f1.w);
    r[4]=pk2(f2.x,f2.y); r[5]=pk2(f2.z,f2.w);
    r[6]=pk2(f3.x,f3.y); r[7]=pk2(f3.z,f3.w);
    float myq = g_sq[b*NN + row];
    float bd[8]; int bi[8];
    #pragma unroll
    for (int p = 0; p < 8; p++) { bd[p] = 3e38f; bi[p] = 0; }

    for (int tt = 0; tt < 32; tt++) {
        __syncthreads();
        const float4* src = (const float4*)g_nodes + ((size_t)b*NN + tt*128)*4;
        scand[t] = src[t];
        scand[t+256] = src[t+256];
        if (t < 128) ssq[t] = g_sq[b*NN + tt*128 + t];
        __syncthreads();
        int base = tt * 128;
        #pragma unroll 4
        for (int j = 0; j < 128; j++) {
            const ulonglong2* cp = (const ulonglong2*)(scand + j*4);
            ulonglong2 ca = cp[0], cb = cp[1], cc = cp[2], cd = cp[3];
            unsigned long long acc = 0ull;
            acc = ffma2(r[0], ca.x, acc); acc = ffma2(r[1], ca.y, acc);
            acc = ffma2(r[2], cb.x, acc); acc = ffma2(r[3], cb.y, acc);
            acc = ffma2(r[4], cc.x, acc); acc = ffma2(r[5], cc.y, acc);
            acc = ffma2(r[6], cd.x, acc); acc = ffma2(r[7], cd.y, acc);
            float dot = unpksum(acc);
            float d = myq + ssq[j] - 2.f * dot;
            int jj = base + j;
            if (d < bd[7] && jj != row) {
                bd[7] = d; bi[7] = jj;
                #pragma unroll
                for (int p = 7; p > 0; p--) {
                    if (bd[p] < bd[p-1]) {
                        float td = bd[p]; bd[p] = bd[p-1]; bd[p-1] = td;
                        int ti = bi[p]; bi[p] = bi[p-1]; bi[p-1] = ti;
                    }
                }
            }
        }
    }

    // ---- GAT aggregation over 8 neighbors + self ----
    float4 adv = ((const float4*)g_adt)[b*NN + row];
    float ad0 = adv.x, ad1 = adv.y, ad2 = adv.z, ad3 = adv.w;
    int idxs[9];
    #pragma unroll
    for (int k = 0; k < 8; k++) idxs[k] = bi[k];
    idxs[8] = row;
    float lg[36];
    float m0 = -3e38f, m1 = -3e38f, m2 = -3e38f, m3 = -3e38f;
    #pragma unroll
    for (int k = 0; k < 9; k++) {
        float4 av = ((const float4*)g_asr)[b*NN + idxs[k]];
        float l0 = av.x + ad0; l0 = l0 > 0.f ? l0 : 0.2f*l0;
        float l1 = av.y + ad1; l1 = l1 > 0.f ? l1 : 0.2f*l1;
        float l2 = av.z + ad2; l2 = l2 > 0.f ? l2 : 0.2f*l2;
        float l3 = av.w + ad3; l3 = l3 > 0.f ? l3 : 0.2f*l3;
        lg[k*4+0] = l0; lg[k*4+1] = l1; lg[k*4+2] = l2; lg[k*4+3] = l3;
        m0 = fmaxf(m0, l0); m1 = fmaxf(m1, l1); m2 = fmaxf(m2, l2); m3 = fmaxf(m3, l3);
    }
    float s0 = 0.f, s1 = 0.f, s2 = 0.f, s3 = 0.f;
    float out[16];
    #pragma unroll
    for (int c = 0; c < 16; c++) out[c] = 0.f;
    #pragma unroll
    for (int k = 0; k < 9; k++) {
        float w0 = expf(lg[k*4+0] - m0);
        float w1 = expf(lg[k*4+1] - m1);
        float w2 = expf(lg[k*4+2] - m2);
        float w3 = expf(lg[k*4+3] - m3);
        s0 += w0; s1 += w1; s2 += w2; s3 += w3;
        const float4* xp4 = (const float4*)g_xp + ((size_t)b*NN + idxs[k])*4;
        float4 x0 = xp4[0], x1 = xp4[1], x2 = xp4[2], x3 = xp4[3];
        out[0]  = fmaf(w0, x0.x, out[0]);  out[1]  = fmaf(w0, x0.y, out[1]);
        out[2]  = fmaf(w0, x0.z, out[2]);  out[3]  = fmaf(w0, x0.w, out[3]);
        out[4]  = fmaf(w1, x1.x, out[4]);  out[5]  = fmaf(w1, x1.y, out[5]);
        out[6]  = fmaf(w1, x1.z, out[6]);  out[7]  = fmaf(w1, x1.w, out[7]);
        out[8]  = fmaf(w2, x2.x, out[8]);  out[9]  = fmaf(w2, x2.y, out[9]);
        out[10] = fmaf(w2, x2.z, out[10]); out[11] = fmaf(w2, x2.w, out[11]);
        out[12] = fmaf(w3, x3.x, out[12]); out[13] = fmaf(w3, x3.y, out[13]);
        out[14] = fmaf(w3, x3.z, out[14]); out[15] = fmaf(w3, x3.w, out[15]);
    }
    float inv0 = 1.f/s0, inv1 = 1.f/s1, inv2 = 1.f/s2, inv3 = 1.f/s3;
    float res[16];
    #pragma unroll
    for (int c = 0; c < 4;  c++) res[c] = fmaxf(out[c]*inv0 + bg[c], 0.f);
    #pragma unroll
    for (int c = 4; c < 8;  c++) res[c] = fmaxf(out[c]*inv1 + bg[c], 0.f);
    #pragma unroll
    for (int c = 8; c < 12; c++) res[c] = fmaxf(out[c]*inv2 + bg[c], 0.f);
    #pragma unroll
    for (int c = 12; c < 16; c++) res[c] = fmaxf(out[c]*inv3 + bg[c], 0.f);
    float4* pd = (float4*)g_p + ((size_t)b*NN + row)*4;
    pd[0] = make_float4(res[0],res[1],res[2],res[3]);
    pd[1] = make_float4(res[4],res[5],res[6],res[7]);
    pd[2] = make_float4(res[8],res[9],res[10],res[11]);
    pd[3] = make_float4(res[12],res[13],res[14],res[15]);
}

// ----------------- update MLP + fire mask + output conv + sigmoid -----------------
__global__ void updk(const float* __restrict__ fire, const float* __restrict__ Wu1,
                     const float* __restrict__ bu1, const float* __restrict__ bu2,
                     const float* __restrict__ Wo,  const float* __restrict__ bo)
{
    __shared__ __align__(16) float sW1[2048];
    __shared__ __align__(16) float sW2[2048];
    __shared__ float sb1[128], sb2[16], sWo[16];
    __shared__ float sbo;
    int t = threadIdx.x;
    for (int i = t; i < 2048; i += 256) { sW1[i] = Wu1[i]; sW2[i] = g_Wu2t[i]; }
    if (t < 128) sb1[t] = bu1[t];
    if (t < 16)  { sb2[t] = bu2[t]; sWo[t] = Wo[t]; }
    if (t == 0)  sbo = bo[0];
    __syncthreads();
    int idx = blockIdx.x * 256 + t;              // 32768
    const float4* pp = (const float4*)g_p + (size_t)idx*4;
    float4 p0 = pp[0], p1 = pp[1], p2 = pp[2], p3 = pp[3];
    float p[16];
    p[0]=p0.x; p[1]=p0.y; p[2]=p0.z; p[3]=p0.w;
    p[4]=p1.x; p[5]=p1.y; p[6]=p1.z; p[7]=p1.w;
    p[8]=p2.x; p[9]=p2.y; p[10]=p2.z; p[11]=p2.w;
    p[12]=p3.x; p[13]=p3.y; p[14]=p3.z; p[15]=p3.w;
    float u[16];
    #pragma unroll
    for (int o = 0; o < 16; o++) u[o] = sb2[o];
    #pragma unroll 4
    for (int h = 0; h < 128; h++) {
        float a = sb1[h];
        #pragma unroll
        for (int c = 0; c < 16; c++) a = fmaf(p[c], sW1[h*16 + c], a);
        a = fmaxf(a, 0.f);
        #pragma unroll
        for (int o = 0; o < 16; o++) u[o] = fmaf(a, sW2[h*16 + o], u[o]);
    }
    float mask = fire[idx] < 0.5f ? 1.f : 0.f;
    const float4* hp = (const float4*)g_nodes + (size_t)idx*4;
    float4 h0 = hp[0], h1 = hp[1], h2 = hp[2], h3 = hp[3];
    float hh[16];
    hh[0]=h0.x; hh[1]=h0.y; hh[2]=h0.z; hh[3]=h0.w;
    hh[4]=h1.x; hh[5]=h1.y; hh[6]=h1.z; hh[7]=h1.w;
    hh[8]=h2.x; hh[9]=h2.y; hh[10]=h2.z; hh[11]=h2.w;
    hh[12]=h3.x; hh[13]=h3.y; hh[14]=h3.z; hh[15]=h3.w;
    float s = sbo;
    #pragma unroll
    for (int c = 0; c < 16; c++) {
        float hn = fmaf(mask, u[c], hh[c]);
        s = fmaf(sWo[c], hn, s);
    }
    g_outlow[idx] = 1.f / (1.f + expf(-s));
}

// ----------------- bilinear 64 -> 256 (jax semantics with edge renorm) -----------------
__global__ void upk(float* __restrict__ out)
{
    int idx = blockIdx.x * 256 + threadIdx.x;        // 524288
    int b = idx >> 16, oy = (idx >> 8) & 255, ox = idx & 255;
    float sy = (oy + 0.5f) * 0.25f - 0.5f;
    float sx = (ox + 0.5f) * 0.25f - 0.5f;
    int y0 = (int)floorf(sy); float fy = sy - (float)y0;
    int x0 = (int)floorf(sx); float fx = sx - (float)x0;
    float wy0 = 1.f - fy, wy1 = fy; int y1 = y0 + 1;
    float wx0 = 1.f - fx, wx1 = fx; int x1 = x0 + 1;
    if (y0 < 0)  { wy0 = 0.f; y0 = 0; }
    if (y1 > 63) { wy1 = 0.f; y1 = 63; }
    if (x0 < 0)  { wx0 = 0.f; x0 = 0; }
    if (x1 > 63) { wx1 = 0.f; x1 = 63; }
    const float* src = g_outlow + b * 4096;
    float v = wy0 * (wx0 * src[y0*64 + x0] + wx1 * src[y0*64 + x1])
            + wy1 * (wx0 * src[y1*64 + x0] + wx1 * src[y1*64 + x1]);
    out[idx] = v / ((wy0 + wy1) * (wx0 + wx1));
}

// ----------------- launch -----------------
extern "C" void kernel_launch(void* const* d_in, const int* in_sizes, int n_in,
                              void* d_out, int out_size)
{
    (void)in_sizes; (void)n_in; (void)out_size;
    const float* x    = (const float*)d_in[0];
    const float* fire = (const float*)d_in[1];
    const float* W1   = (const float*)d_in[2];
    const float* b1   = (const float*)d_in[3];
    const float* g1   = (const float*)d_in[4];
    const float* be1  = (const float*)d_in[5];
    const float* m1   = (const float*)d_in[6];
    const float* v1   = (const float*)d_in[7];
    const float* W2   = (const float*)d_in[8];
    const float* b2   = (const float*)d_in[9];
    const float* g2   = (const float*)d_in[10];
    const float* be2  = (const float*)d_in[11];
    const float* m2   = (const float*)d_in[12];
    const float* v2   = (const float*)d_in[13];
    const float* Wg   = (const float*)d_in[14];
    const float* a_src= (const float*)d_in[15];
    const float* a_dst= (const float*)d_in[16];
    const float* bg   = (const float*)d_in[17];
    const float* Wu1  = (const float*)d_in[18];
    const float* bu1  = (const float*)d_in[19];
    const float* Wu2  = (const float*)d_in[20];
    const float* bu2  = (const float*)d_in[21];
    const float* Wo   = (const float*)d_in[22];
    const float* bo   = (const float*)d_in[23];
    float* out = (float*)d_out;

    prepk<<<1, 256>>>(W1, b1, g1, be1, m1, v1, W2, b2, g2, be2, m2, v2, Wu2);
    downk<<<128, 256>>>(x);
    conv1k<<<128, 256>>>();
    conv2k<<<dim3(4, 4, 8), 256>>>();
    featk<<<128, 256>>>(Wg, a_src, a_dst);
    knnk<<<dim3(16, 8), 256>>>(bg);
    updk<<<128, 256>>>(fire, Wu1, bu1, bu2, Wo, bo);
    upk<<<2048, 256>>>(out);
}